// round 1
// baseline (speedup 1.0000x reference)
#include <cuda_runtime.h>

#define NN 4096
#define BB 8
#define CHUNK 64
#define NCHUNK (NN / CHUNK)
#define TPB 256

// strength(v) = (e^v - e^-1) / (e - e^-1) = C1 * e^v - C2
#define C1 0.4254590641196608f
#define C2 0.1565176423029702f

// Partial sums: [NCHUNK][B][N] floats = 8 MB device-global scratch.
__device__ float g_partial[NCHUNK * BB * NN];

__global__ __launch_bounds__(TPB) void pair_kernel(
    const float* __restrict__ x,
    const float* __restrict__ position,
    const float* __restrict__ indir,
    const float* __restrict__ outdir)
{
    // Per-sender record: rec[i][0] = (px, py, pz, ox)
    //                    rec[i][1] = (oy, oz, --, --)
    //                    rec[i][2] = (x0, x1, x2, x3)
    //                    rec[i][3] = (x4, x5, x6, x7)
    __shared__ float4 rec[CHUNK][4];

    const int tid = threadIdx.x;
    const int j  = blockIdx.x * TPB + tid;     // receiver index
    const int i0 = blockIdx.y * CHUNK;         // sender chunk base

    // Cooperative load: 64 records * 4 float4 = 256 float4, one per thread.
    {
        const int r = tid >> 2;
        const int f = tid & 3;
        const int i = i0 + r;
        float4 v;
        if (f == 0) {
            v = make_float4(position[i * 3 + 0], position[i * 3 + 1],
                            position[i * 3 + 2], outdir[i * 3 + 0]);
        } else if (f == 1) {
            v = make_float4(outdir[i * 3 + 1], outdir[i * 3 + 2], 0.f, 0.f);
        } else if (f == 2) {
            v = make_float4(x[0 * NN + i], x[1 * NN + i],
                            x[2 * NN + i], x[3 * NN + i]);
        } else {
            v = make_float4(x[4 * NN + i], x[5 * NN + i],
                            x[6 * NN + i], x[7 * NN + i]);
        }
        rec[r][f] = v;
    }

    // Receiver-side data (held in registers for the whole chunk)
    const float pjx = position[j * 3 + 0];
    const float pjy = position[j * 3 + 1];
    const float pjz = position[j * 3 + 2];
    const float inx = indir[j * 3 + 0];
    const float iny = indir[j * 3 + 1];
    const float inz = indir[j * 3 + 2];

    __syncthreads();

    float a0 = 0.f, a1 = 0.f, a2 = 0.f, a3 = 0.f;
    float a4 = 0.f, a5 = 0.f, a6 = 0.f, a7 = 0.f;

#pragma unroll 8
    for (int ii = 0; ii < CHUNK; ii++) {
        const float4 A  = rec[ii][0];
        const float4 Bv = rec[ii][1];

        // delta_p[i, j] = pos[j] - pos[i]
        const float dx = pjx - A.x;
        const float dy = pjy - A.y;
        const float dz = pjz - A.z;

        const float n2 = fmaf(dx, dx, fmaf(dy, dy, dz * dz));
        const float rn = rsqrtf(fmaxf(n2, 1e-5f));

        // alpha dot: delta . outdir_i ; beta dot: delta . indir_j
        const float da = fmaf(dx, A.w, fmaf(dy, Bv.x, dz * Bv.y));
        const float db = fmaf(dx, inx, fmaf(dy, iny, dz * inz));

        const float sa = fmaf(C1, __expf(da * rn), -C2);
        const float sb = fmaf(C1, __expf(db * rn), -C2);
        const float g  = sa * sb;

        const float4 X0 = rec[ii][2];
        const float4 X1 = rec[ii][3];
        a0 = fmaf(g, X0.x, a0);
        a1 = fmaf(g, X0.y, a1);
        a2 = fmaf(g, X0.z, a2);
        a3 = fmaf(g, X0.w, a3);
        a4 = fmaf(g, X1.x, a4);
        a5 = fmaf(g, X1.y, a5);
        a6 = fmaf(g, X1.z, a6);
        a7 = fmaf(g, X1.w, a7);
    }

    float* outp = g_partial + (size_t)(blockIdx.y * BB) * NN + j;
    outp[0 * NN] = a0;
    outp[1 * NN] = a1;
    outp[2 * NN] = a2;
    outp[3 * NN] = a3;
    outp[4 * NN] = a4;
    outp[5 * NN] = a5;
    outp[6 * NN] = a6;
    outp[7 * NN] = a7;
}

__global__ __launch_bounds__(256) void reduce_kernel(
    const float* __restrict__ power,
    const float* __restrict__ bias,
    float* __restrict__ out)
{
    const int t = blockIdx.x * 256 + threadIdx.x;   // t in [0, B*N)
    const int b = t >> 12;                          // / 4096
    const int j = t & (NN - 1);                     // % 4096

    float s = 0.f;
#pragma unroll 8
    for (int c = 0; c < NCHUNK; c++) {
        s += g_partial[(size_t)(c * BB + b) * NN + j];
    }

    const float z = fmaf(s, power[j], -bias[j]);
    out[t] = (z > 0.f) ? z : expm1f(z);
}

extern "C" void kernel_launch(void* const* d_in, const int* in_sizes, int n_in,
                              void* d_out, int out_size)
{
    const float* x        = (const float*)d_in[0];
    const float* position = (const float*)d_in[1];
    const float* indir    = (const float*)d_in[2];
    const float* outdir   = (const float*)d_in[3];
    const float* power    = (const float*)d_in[4];
    const float* bias     = (const float*)d_in[5];
    float* out = (float*)d_out;

    dim3 grid(NN / TPB, NCHUNK);
    pair_kernel<<<grid, TPB>>>(x, position, indir, outdir);
    reduce_kernel<<<(BB * NN) / 256, 256>>>(power, bias, out);
}